// round 14
// baseline (speedup 1.0000x reference)
#include <cuda_runtime.h>
#include <cuda_fp16.h>
#include <mma.h>
#include <cstdint>
#include <cstddef>

using namespace nvcuda;

// Problem constants
#define BATCH 2
#define SEQ   2048
#define DIM   1024
#define NH    16
#define HD    64
// ATT_SCALE * log2(e): S = (Q@K^T)*scale comes out in log2 domain -> exp = ex2
#define ATT_SCALE_LOG2E 0.1803368801111244f
#define MBW   (SEQ / 32)
#define MTOT  (BATCH * SEQ)   // 4096

// Scratch (all fp16 intermediates)
__device__ __half g_Xh[3 * MTOT * DIM];    // converted query,key,value
__device__ __half g_Wh[4 * DIM * DIM];     // converted Wq,Wk,Wv,Wo
__device__ __half g_QKVh[3 * MTOT * DIM];  // projected Q,K,V
__device__ __half g_Ch[MTOT * DIM];        // attention context
__device__ uint32_t g_MB[SEQ * MBW];       // mask bit words

// ---------------------------------------------------------------------------
// PTX helpers
// ---------------------------------------------------------------------------
__device__ __forceinline__ uint32_t smemu32(const void* p) {
    return (uint32_t)__cvta_generic_to_shared(p);
}
__device__ __forceinline__ void cp16(uint32_t saddr, const void* g) {
    asm volatile("cp.async.cg.shared.global [%0], [%1], 16;" :: "r"(saddr), "l"(g));
}
__device__ __forceinline__ void cp_commit() { asm volatile("cp.async.commit_group;"); }
__device__ __forceinline__ void cp_wait1()  { asm volatile("cp.async.wait_group 1;"); }
__device__ __forceinline__ void cp_wait2()  { asm volatile("cp.async.wait_group 2;"); }

__device__ __forceinline__ void ldsm4(uint32_t* r, uint32_t a) {
    asm volatile("ldmatrix.sync.aligned.m8n8.x4.shared.b16 {%0,%1,%2,%3}, [%4];"
        : "=r"(r[0]), "=r"(r[1]), "=r"(r[2]), "=r"(r[3]) : "r"(a));
}
__device__ __forceinline__ void ldsm4t(uint32_t* r, uint32_t a) {
    asm volatile("ldmatrix.sync.aligned.m8n8.x4.trans.shared.b16 {%0,%1,%2,%3}, [%4];"
        : "=r"(r[0]), "=r"(r[1]), "=r"(r[2]), "=r"(r[3]) : "r"(a));
}
__device__ __forceinline__ void mma16816(float& c0, float& c1, float& c2, float& c3,
                                         uint32_t a0, uint32_t a1, uint32_t a2, uint32_t a3,
                                         uint32_t b0, uint32_t b1) {
    asm volatile("mma.sync.aligned.m16n8k16.row.col.f32.f16.f16.f32 "
                 "{%0,%1,%2,%3}, {%4,%5,%6,%7}, {%8,%9}, {%0,%1,%2,%3};"
                 : "+f"(c0), "+f"(c1), "+f"(c2), "+f"(c3)
                 : "r"(a0), "r"(a1), "r"(a2), "r"(a3), "r"(b0), "r"(b1));
}
__device__ __forceinline__ uint32_t pack_h2(float a, float b) {
    __half2 h = __floats2half2_rn(a, b);
    return *reinterpret_cast<uint32_t*>(&h);
}
// 2^x on the MUFU pipe (input already in log2 domain)
__device__ __forceinline__ float ex2f(float x) {
    float y;
    asm("ex2.approx.f32 %0, %1;" : "=f"(y) : "f"(x));
    return y;
}

// ---------------------------------------------------------------------------
// Pre-pass kernels: mask bits + fp32->fp16 conversion
// ---------------------------------------------------------------------------
__global__ __launch_bounds__(256)
void mask_bits_kernel(const int* __restrict__ mask)
{
    int idx = blockIdx.x * 256 + threadIdx.x;
    uint32_t bit = (mask[idx] != 0) ? 1u : 0u;
    uint32_t word = __ballot_sync(0xffffffffu, bit);
    if ((threadIdx.x & 31) == 0) g_MB[idx >> 5] = word;
}

__global__ __launch_bounds__(256)
void cvt_inputs(const float* __restrict__ q, const float* __restrict__ k,
                const float* __restrict__ v)
{
    const float* src = (blockIdx.y == 0) ? q : (blockIdx.y == 1) ? k : v;
    __half* dst = g_Xh + (size_t)blockIdx.y * MTOT * DIM;
    int i = blockIdx.x * 256 + threadIdx.x;
    float4 x = reinterpret_cast<const float4*>(src)[i];
    __half2* d = reinterpret_cast<__half2*>(dst + (size_t)i * 4);
    d[0] = __floats2half2_rn(x.x, x.y);
    d[1] = __floats2half2_rn(x.z, x.w);
}

__global__ __launch_bounds__(256)
void cvt_weights(const float* __restrict__ w0, const float* __restrict__ w1,
                 const float* __restrict__ w2, const float* __restrict__ w3)
{
    const float* src = (blockIdx.y == 0) ? w0 : (blockIdx.y == 1) ? w1
                     : (blockIdx.y == 2) ? w2 : w3;
    __half* dst = g_Wh + (size_t)blockIdx.y * DIM * DIM;
    int i = blockIdx.x * 256 + threadIdx.x;
    float4 x = reinterpret_cast<const float4*>(src)[i];
    __half2* d = reinterpret_cast<__half2*>(dst + (size_t)i * 4);
    d[0] = __floats2half2_rn(x.x, x.y);
    d[1] = __floats2half2_rn(x.z, x.w);
}

// ---------------------------------------------------------------------------
// All-half GEMM + bias (+scale): C = (A @ W + bias) * scale
// 128x128x32 tile, 4-stage cp.async pipeline, 8 warps (2m x 4n), warp 64x32.
// ---------------------------------------------------------------------------
#define GBM 128
#define GBN 128
#define GBK 32
#define A_LDH 40
#define B_LDH 136
#define GSTG 4
#define G_A_ELT (GBM * A_LDH)                 // 5120 halves per A stage
#define G_B_ELT (GBK * B_LDH)                 // 4352 halves per B stage
#define GEMM_SMEM ((GSTG * (G_A_ELT + G_B_ELT)) * 2)   // 75776 bytes

template <typename OT>
__global__ __launch_bounds__(256, 2)
void gemm_h(const __half* __restrict__ Abase, size_t sA,
            const __half* __restrict__ Wbase, size_t sW,
            const float* __restrict__ b0, const float* __restrict__ b1,
            const float* __restrict__ b2,
            OT* __restrict__ Cbase, size_t sC,
            float sc0, float sc1, float sc2)
{
    extern __shared__ __half gsm[];
    __half* As = gsm;                          // [GSTG][G_A_ELT]
    __half* Bs = gsm + GSTG * G_A_ELT;         // [GSTG][G_B_ELT]

    const int z = blockIdx.z;
    const __half* A = Abase + (size_t)z * sA;
    const __half* W = Wbase + (size_t)z * sW;
    const float* bias = (z == 0) ? b0 : (z == 1) ? b1 : b2;
    OT* C = Cbase + (size_t)z * sC;
    const float sc = (z == 0) ? sc0 : (z == 1) ? sc1 : sc2;

    const int tid = threadIdx.x, lane = tid & 31, w = tid >> 5;
    const int wm = w >> 2, wn = w & 3;          // warp: rows wm*64, cols wn*32
    const int row0 = blockIdx.y * GBM, col0 = blockIdx.x * GBN;
    const int N = DIM, K = DIM;

    wmma::fragment<wmma::accumulator, 16, 16, 16, float> acc[4][2];
#pragma unroll
    for (int mf = 0; mf < 4; mf++)
#pragma unroll
        for (int nf = 0; nf < 2; nf++)
            wmma::fill_fragment(acc[mf][nf], 0.f);

    auto stage = [&](int buf, int kt) {
        __half* Ad = As + buf * G_A_ELT;
        __half* Bd = Bs + buf * G_B_ELT;
#pragma unroll
        for (int it = 0; it < 2; it++) {
            int c = tid + it * 256;
            int arow = c >> 2, acu = c & 3;
            cp16(smemu32(&Ad[arow * A_LDH + acu * 8]),
                 A + (size_t)(row0 + arow) * K + kt + acu * 8);
            int brow = c >> 4, bcu = c & 15;
            cp16(smemu32(&Bd[brow * B_LDH + bcu * 8]),
                 W + (size_t)(kt + brow) * N + col0 + bcu * 8);
        }
    };

    // prolog: fill 3 stages
#pragma unroll
    for (int s = 0; s < GSTG - 1; s++) {
        stage(s, s * GBK);
        cp_commit();
    }

    const int NIT = K / GBK;   // 32
    for (int i = 0; i < NIT; i++) {
        cp_wait2();
        __syncthreads();
        if (i + GSTG - 1 < NIT) stage((i + GSTG - 1) % GSTG, (i + GSTG - 1) * GBK);
        cp_commit();

        const __half* sAp = As + (i % GSTG) * G_A_ELT;
        const __half* sBp = Bs + (i % GSTG) * G_B_ELT;
#pragma unroll
        for (int ks = 0; ks < 2; ks++) {
            const int k0 = ks * 16;
            wmma::fragment<wmma::matrix_a, 16, 16, 16, __half, wmma::row_major> af[4];
            wmma::fragment<wmma::matrix_b, 16, 16, 16, __half, wmma::row_major> bf[2];
#pragma unroll
            for (int mf = 0; mf < 4; mf++)
                wmma::load_matrix_sync(af[mf], &sAp[(wm * 64 + mf * 16) * A_LDH + k0], A_LDH);
#pragma unroll
            for (int nf = 0; nf < 2; nf++)
                wmma::load_matrix_sync(bf[nf], &sBp[k0 * B_LDH + wn * 32 + nf * 16], B_LDH);
#pragma unroll
            for (int mf = 0; mf < 4; mf++)
#pragma unroll
                for (int nf = 0; nf < 2; nf++)
                    wmma::mma_sync(acc[mf][nf], af[mf], bf[nf], acc[mf][nf]);
        }
    }

    // epilogue: (acc + bias) * scale
    float2 bb[2][2];
#pragma unroll
    for (int nf = 0; nf < 2; nf++)
#pragma unroll
        for (int g = 0; g < 2; g++)
            bb[nf][g] = *reinterpret_cast<const float2*>(
                &bias[col0 + wn * 32 + nf * 16 + g * 8 + 2 * (lane & 3)]);

#pragma unroll
    for (int mf = 0; mf < 4; mf++) {
        const int r = row0 + wm * 64 + mf * 16 + (lane >> 2);
#pragma unroll
        for (int nf = 0; nf < 2; nf++) {
#pragma unroll
            for (int g = 0; g < 2; g++) {
                const int col = col0 + wn * 32 + nf * 16 + g * 8 + 2 * (lane & 3);
                float v0 = (acc[mf][nf].x[g * 4 + 0] + bb[nf][g].x) * sc;
                float v1 = (acc[mf][nf].x[g * 4 + 1] + bb[nf][g].y) * sc;
                float v2 = (acc[mf][nf].x[g * 4 + 2] + bb[nf][g].x) * sc;
                float v3 = (acc[mf][nf].x[g * 4 + 3] + bb[nf][g].y) * sc;
                if constexpr (__is_same(OT, float)) {
                    *reinterpret_cast<float2*>(&C[(size_t)r * N + col])       = make_float2(v0, v1);
                    *reinterpret_cast<float2*>(&C[(size_t)(r + 8) * N + col]) = make_float2(v2, v3);
                } else {
                    *reinterpret_cast<__half2*>(&C[(size_t)r * N + col])       = __floats2half2_rn(v0, v1);
                    *reinterpret_cast<__half2*>(&C[(size_t)(r + 8) * N + col]) = __floats2half2_rn(v2, v3);
                }
            }
        }
    }
}

// ---------------------------------------------------------------------------
// FA2-style masked attention on raw mma.m16n8k16.
// 8 warps x 16 Q rows (128-row Q tile), KV tile 64, 3-stage cp.async pipeline.
// S arrives in the log2 domain (log2e folded into Q scale) -> softmax
// numerator is ONE MUFU ex2 per value. Row-sum shuffles hoisted out of loop.
// ---------------------------------------------------------------------------
#define ALD 72
#define ASTG 3

__global__ __launch_bounds__(256, 2)
void attn_mma(__half* __restrict__ Og)
{
    extern __shared__ __half sm[];
    __half* Qs = sm;                    // [128][72]
    __half* Ks = Qs + 128 * ALD;        // [3][64][72]
    __half* Vs = Ks + ASTG * 64 * ALD;  // [3][64][72]

    const int qt = blockIdx.x, h = blockIdx.y, b = blockIdx.z;
    const int s0 = qt * 128;
    const int tid = threadIdx.x, lane = tid & 31, w = tid >> 5;
    const int grp = lane >> 2, tig = lane & 3;
    const int q0 = w * 16;

    const __half* Qb = g_QKVh + ((size_t)b * SEQ + s0) * DIM + h * HD;
    const __half* Kb = g_QKVh + (size_t)MTOT * DIM + (size_t)b * SEQ * DIM + h * HD;
    const __half* Vb = g_QKVh + 2 * (size_t)MTOT * DIM + (size_t)b * SEQ * DIM + h * HD;

    // stage Q tile (log2-domain scale pre-folded): 1024 uint4, 4/thread
#pragma unroll
    for (int it = 0; it < 4; it++) {
        int lin = tid + it * 256, r = lin >> 3, u = lin & 7;
        *reinterpret_cast<uint4*>(&Qs[r * ALD + u * 8]) =
            *reinterpret_cast<const uint4*>(Qb + (size_t)r * DIM + u * 8);
    }

    // cp.async KV staging: 512 chunks per matrix, 2/thread each
    const int kr0 = tid >> 3, ku = tid & 7, kr1 = kr0 + 32;
    auto stage_kv = [&](int buf, int kt) {
        __half* Kd = Ks + buf * 64 * ALD;
        __half* Vd = Vs + buf * 64 * ALD;
        cp16(smemu32(&Kd[kr0 * ALD + ku * 8]), Kb + (size_t)(kt + kr0) * DIM + ku * 8);
        cp16(smemu32(&Kd[kr1 * ALD + ku * 8]), Kb + (size_t)(kt + kr1) * DIM + ku * 8);
        cp16(smemu32(&Vd[kr0 * ALD + ku * 8]), Vb + (size_t)(kt + kr0) * DIM + ku * 8);
        cp16(smemu32(&Vd[kr1 * ALD + ku * 8]), Vb + (size_t)(kt + kr1) * DIM + ku * 8);
    };
    stage_kv(0, 0);
    cp_commit();
    stage_kv(1, 64);
    cp_commit();
    __syncthreads();   // Qs visible for ldmatrix

    // persistent Q A-fragments
    uint32_t qa[4][4];
#pragma unroll
    for (int di = 0; di < 4; di++) {
        uint32_t a = smemu32(&Qs[(q0 + (lane & 15)) * ALD + di * 16 + 8 * (lane >> 4)]);
        ldsm4(qa[di], a);
    }

    float o[8][4];
#pragma unroll
    for (int j = 0; j < 8; j++)
#pragma unroll
        for (int e = 0; e < 4; e++) o[j][e] = 0.f;
    float lsum0 = 0.f, lsum8 = 0.f;    // per-thread partials; reduced after loop

    const int mrow0 = (s0 + q0 + grp) * MBW;

    const int NIT = SEQ / 64;   // 32
    for (int i = 0; i < NIT; i++) {
        cp_wait1();
        __syncthreads();
        if (i + 2 < NIT) stage_kv((i + 2) % ASTG, (i + 2) * 64);
        cp_commit();

        const __half* Kt = Ks + (i % ASTG) * 64 * ALD;
        const __half* Vt = Vs + (i % ASTG) * 64 * ALD;
        const int kt = i * 64;

        // mask words for this warp's two row-halves
        const int wi = kt >> 5;
        uint32_t mlo0 = g_MB[mrow0 + wi],           mlo1 = g_MB[mrow0 + wi + 1];
        uint32_t mhi0 = g_MB[mrow0 + 8 * MBW + wi], mhi1 = g_MB[mrow0 + 8 * MBW + wi + 1];

        // ---- S = Q @ K^T (log2 domain) : 16 x 64 strip per warp ----
        float s[8][4];
#pragma unroll
        for (int j = 0; j < 8; j++)
#pragma unroll
            for (int e = 0; e < 4; e++) s[j][e] = 0.f;

#pragma unroll
        for (int di = 0; di < 4; di++) {
            const int d0 = di * 16;
            uint32_t kb[4][4];
#pragma unroll
            for (int ti = 0; ti < 4; ti++) {
                uint32_t a = smemu32(&Kt[(ti * 16 + (lane & 7) + 8 * (lane >> 4)) * ALD
                                         + d0 + 8 * ((lane >> 3) & 1)]);
                ldsm4(kb[ti], a);
            }
#pragma unroll
            for (int ti = 0; ti < 4; ti++) {
                const int j = 2 * ti;
                mma16816(s[j][0], s[j][1], s[j][2], s[j][3],
                         qa[di][0], qa[di][1], qa[di][2], qa[di][3], kb[ti][0], kb[ti][1]);
                mma16816(s[j + 1][0], s[j + 1][1], s[j + 1][2], s[j + 1][3],
                         qa[di][0], qa[di][1], qa[di][2], qa[di][3], kb[ti][2], kb[ti][3]);
            }
        }

        // ---- masked ex2 + row-sum partials + pack P (registers only) ----
        uint32_t ph[8][2];
#pragma unroll
        for (int j = 0; j < 8; j++) {
            uint32_t wlo = (j < 4) ? mlo0 : mlo1;
            uint32_t whi = (j < 4) ? mhi0 : mhi1;
            const int bit = (8 * j + 2 * tig) & 31;
            float p0 = ((wlo >> bit) & 1u)       ? ex2f(s[j][0]) : 0.f;
            float p1 = ((wlo >> (bit + 1)) & 1u) ? ex2f(s[j][1]) : 0.f;
            float p2 = ((whi >> bit) & 1u)       ? ex2f(s[j][2]) : 0.f;
            float p3 = ((whi >> (bit + 1)) & 1u) ? ex2f(s[j][3]) : 0.f;
            lsum0 += p0 + p1;
            lsum8 += p2 + p3;
            ph[j][0] = pack_h2(p0, p1);
            ph[j][1] = pack_h2(p2, p3);
        }

        // ---- O += P @ V (P from registers, V ldsm batched per ti) ----
#pragma unroll
        for (int ti = 0; ti < 4; ti++) {
            const int t0 = ti * 16, j = 2 * ti;
            uint32_t vb[4][4];
#pragma unroll
            for (int ni = 0; ni < 4; ni++) {
                uint32_t a = smemu32(&Vt[(t0 + (lane & 15)) * ALD + ni * 16 + 8 * (lane >> 4)]);
                ldsm4t(vb[ni], a);
            }
#pragma unroll
            for (int ni = 0; ni < 4; ni++) {
                const int jo = 2 * ni;
                mma16816(o[jo][0], o[jo][1], o[jo][2], o[jo][3],
                         ph[j][0], ph[j][1], ph[j + 1][0], ph[j + 1][1], vb[ni][0], vb[ni][1]);
                mma16816(o[jo + 1][0], o[jo + 1][1], o[jo + 1][2], o[jo + 1][3],
                         ph[j][0], ph[j][1], ph[j + 1][0], ph[j + 1][1], vb[ni][2], vb[ni][3]);
            }
        }
    }

    // ---- final row-sum reduction (once, not per tile) ----
    lsum0 += __shfl_xor_sync(0xffffffffu, lsum0, 1);
    lsum0 += __shfl_xor_sync(0xffffffffu, lsum0, 2);
    lsum8 += __shfl_xor_sync(0xffffffffu, lsum8, 1);
    lsum8 += __shfl_xor_sync(0xffffffffu, lsum8, 2);

    // ---- normalize + write half ctx ----
    const float inv0 = 1.f / lsum0;
    const float inv8 = 1.f / lsum8;
    __half* O0 = Og + ((size_t)b * SEQ + s0 + q0 + grp) * DIM + h * HD;
    __half* O8 = O0 + 8 * (size_t)DIM;
#pragma unroll
    for (int j = 0; j < 8; j++) {
        const int col = 8 * j + 2 * tig;
        *reinterpret_cast<__half2*>(&O0[col]) = __floats2half2_rn(o[j][0] * inv0, o[j][1] * inv0);
        *reinterpret_cast<__half2*>(&O8[col]) = __floats2half2_rn(o[j][2] * inv8, o[j][3] * inv8);
    }
}

// ---------------------------------------------------------------------------
// Launch
// ---------------------------------------------------------------------------
extern "C" void kernel_launch(void* const* d_in, const int* in_sizes, int n_in,
                              void* d_out, int out_size)
{
    const float* query = (const float*)d_in[0];
    const float* key   = (const float*)d_in[1];
    const float* value = (const float*)d_in[2];
    const int*   mask  = (const int*)  d_in[3];
    const float* Wq = (const float*)d_in[4];
    const float* bq = (const float*)d_in[5];
    const float* Wk = (const float*)d_in[6];
    const float* bk = (const float*)d_in[7];
    const float* Wv = (const float*)d_in[8];
    const float* bv = (const float*)d_in[9];
    const float* Wo = (const float*)d_in[10];
    const float* bo = (const float*)d_in[11];
    float* out = (float*)d_out;

    __half *pXh, *pWh, *pQKV, *pC;
    cudaGetSymbolAddress((void**)&pXh,  g_Xh);
    cudaGetSymbolAddress((void**)&pWh,  g_Wh);
    cudaGetSymbolAddress((void**)&pQKV, g_QKVh);
    cudaGetSymbolAddress((void**)&pC,   g_Ch);

    // pre-passes
    mask_bits_kernel<<<SEQ * SEQ / 256, 256>>>(mask);
    cvt_inputs<<<dim3(MTOT * DIM / 4 / 256, 3), 256>>>(query, key, value);
    cvt_weights<<<dim3(DIM * DIM / 4 / 256, 4), 256>>>(Wq, Wk, Wv, Wo);

    // fused QKV projections (all-half), log2-domain scale folded into Q
    cudaFuncSetAttribute(gemm_h<__half>, cudaFuncAttributeMaxDynamicSharedMemorySize, GEMM_SMEM);
    cudaFuncSetAttribute(gemm_h<float>,  cudaFuncAttributeMaxDynamicSharedMemorySize, GEMM_SMEM);
    dim3 qkv_grid(DIM / GBN, MTOT / GBM, 3);   // (8, 32, 3)
    gemm_h<__half><<<qkv_grid, 256, GEMM_SMEM>>>(
        pXh, (size_t)MTOT * DIM, pWh, (size_t)DIM * DIM,
        bq, bk, bv, pQKV, (size_t)MTOT * DIM,
        ATT_SCALE_LOG2E, 1.0f, 1.0f);

    // attention (3-stage KV pipeline, ex2-domain softmax)
    const int attn_smem = (128 + 2 * ASTG * 64) * ALD * (int)sizeof(__half);  // 73728 B
    cudaFuncSetAttribute(attn_mma, cudaFuncAttributeMaxDynamicSharedMemorySize, attn_smem);
    attn_mma<<<dim3(SEQ / 128, NH, BATCH), 256, attn_smem>>>(pC);

    // output projection (half A -> fp32 out)
    dim3 ogrid(DIM / GBN, MTOT / GBM, 1);
    gemm_h<float><<<ogrid, 256, GEMM_SMEM>>>(
        pC, 0, pWh + 3 * (size_t)DIM * DIM, 0,
        bo, bo, bo, out, 0,
        1.0f, 1.0f, 1.0f);
}

// round 15
// speedup vs baseline: 1.0078x; 1.0078x over previous
#include <cuda_runtime.h>
#include <cuda_fp16.h>
#include <mma.h>
#include <cstdint>
#include <cstddef>

using namespace nvcuda;

// Problem constants
#define BATCH 2
#define SEQ   2048
#define DIM   1024
#define NH    16
#define HD    64
// ATT_SCALE * log2(e): S = (Q@K^T)*scale comes out in log2 domain -> exp = ex2
#define ATT_SCALE_LOG2E 0.1803368801111244f
#define MBW   (SEQ / 32)
#define MTOT  (BATCH * SEQ)   // 4096

// Scratch (all fp16 intermediates)
__device__ __half g_Xh[3 * MTOT * DIM];    // converted query,key,value
__device__ __half g_Wh[4 * DIM * DIM];     // converted Wq,Wk,Wv,Wo
__device__ __half g_QKVh[3 * MTOT * DIM];  // projected Q,K,V
__device__ __half g_Ch[MTOT * DIM];        // attention context
__device__ uint32_t g_MB[SEQ * MBW];       // mask bit words

// ---------------------------------------------------------------------------
// PTX helpers
// ---------------------------------------------------------------------------
__device__ __forceinline__ uint32_t smemu32(const void* p) {
    return (uint32_t)__cvta_generic_to_shared(p);
}
__device__ __forceinline__ void cp16(uint32_t saddr, const void* g) {
    asm volatile("cp.async.cg.shared.global [%0], [%1], 16;" :: "r"(saddr), "l"(g));
}
__device__ __forceinline__ void cp_commit() { asm volatile("cp.async.commit_group;"); }
__device__ __forceinline__ void cp_wait1()  { asm volatile("cp.async.wait_group 1;"); }
__device__ __forceinline__ void cp_wait2()  { asm volatile("cp.async.wait_group 2;"); }

__device__ __forceinline__ void ldsm4(uint32_t* r, uint32_t a) {
    asm volatile("ldmatrix.sync.aligned.m8n8.x4.shared.b16 {%0,%1,%2,%3}, [%4];"
        : "=r"(r[0]), "=r"(r[1]), "=r"(r[2]), "=r"(r[3]) : "r"(a));
}
__device__ __forceinline__ void ldsm4t(uint32_t* r, uint32_t a) {
    asm volatile("ldmatrix.sync.aligned.m8n8.x4.trans.shared.b16 {%0,%1,%2,%3}, [%4];"
        : "=r"(r[0]), "=r"(r[1]), "=r"(r[2]), "=r"(r[3]) : "r"(a));
}
__device__ __forceinline__ void mma16816(float& c0, float& c1, float& c2, float& c3,
                                         uint32_t a0, uint32_t a1, uint32_t a2, uint32_t a3,
                                         uint32_t b0, uint32_t b1) {
    asm volatile("mma.sync.aligned.m16n8k16.row.col.f32.f16.f16.f32 "
                 "{%0,%1,%2,%3}, {%4,%5,%6,%7}, {%8,%9}, {%0,%1,%2,%3};"
                 : "+f"(c0), "+f"(c1), "+f"(c2), "+f"(c3)
                 : "r"(a0), "r"(a1), "r"(a2), "r"(a3), "r"(b0), "r"(b1));
}
__device__ __forceinline__ uint32_t pack_h2(float a, float b) {
    __half2 h = __floats2half2_rn(a, b);
    return *reinterpret_cast<uint32_t*>(&h);
}
// 2^x on the MUFU pipe (input already in log2 domain)
__device__ __forceinline__ float ex2f(float x) {
    float y;
    asm("ex2.approx.f32 %0, %1;" : "=f"(y) : "f"(x));
    return y;
}

// ---------------------------------------------------------------------------
// Pre-pass kernels: mask bits + fp32->fp16 conversion
// ---------------------------------------------------------------------------
__global__ __launch_bounds__(256)
void mask_bits_kernel(const int* __restrict__ mask)
{
    int idx = blockIdx.x * 256 + threadIdx.x;
    uint32_t bit = (mask[idx] != 0) ? 1u : 0u;
    uint32_t word = __ballot_sync(0xffffffffu, bit);
    if ((threadIdx.x & 31) == 0) g_MB[idx >> 5] = word;
}

__global__ __launch_bounds__(256)
void cvt_inputs(const float* __restrict__ q, const float* __restrict__ k,
                const float* __restrict__ v)
{
    const float* src = (blockIdx.y == 0) ? q : (blockIdx.y == 1) ? k : v;
    __half* dst = g_Xh + (size_t)blockIdx.y * MTOT * DIM;
    int i = blockIdx.x * 256 + threadIdx.x;
    float4 x = reinterpret_cast<const float4*>(src)[i];
    __half2* d = reinterpret_cast<__half2*>(dst + (size_t)i * 4);
    d[0] = __floats2half2_rn(x.x, x.y);
    d[1] = __floats2half2_rn(x.z, x.w);
}

__global__ __launch_bounds__(256)
void cvt_weights(const float* __restrict__ w0, const float* __restrict__ w1,
                 const float* __restrict__ w2, const float* __restrict__ w3)
{
    const float* src = (blockIdx.y == 0) ? w0 : (blockIdx.y == 1) ? w1
                     : (blockIdx.y == 2) ? w2 : w3;
    __half* dst = g_Wh + (size_t)blockIdx.y * DIM * DIM;
    int i = blockIdx.x * 256 + threadIdx.x;
    float4 x = reinterpret_cast<const float4*>(src)[i];
    __half2* d = reinterpret_cast<__half2*>(dst + (size_t)i * 4);
    d[0] = __floats2half2_rn(x.x, x.y);
    d[1] = __floats2half2_rn(x.z, x.w);
}

// ---------------------------------------------------------------------------
// All-half GEMM + bias (+scale): C = (A @ W + bias) * scale
// 128x128x32 tile, 4-stage cp.async pipeline, 8 warps (2m x 4n), warp 64x32.
// ---------------------------------------------------------------------------
#define GBM 128
#define GBN 128
#define GBK 32
#define A_LDH 40
#define B_LDH 136
#define GSTG 4
#define G_A_ELT (GBM * A_LDH)                 // 5120 halves per A stage
#define G_B_ELT (GBK * B_LDH)                 // 4352 halves per B stage
#define GEMM_SMEM ((GSTG * (G_A_ELT + G_B_ELT)) * 2)   // 75776 bytes

template <typename OT>
__global__ __launch_bounds__(256, 2)
void gemm_h(const __half* __restrict__ Abase, size_t sA,
            const __half* __restrict__ Wbase, size_t sW,
            const float* __restrict__ b0, const float* __restrict__ b1,
            const float* __restrict__ b2,
            OT* __restrict__ Cbase, size_t sC,
            float sc0, float sc1, float sc2)
{
    extern __shared__ __half gsm[];
    __half* As = gsm;                          // [GSTG][G_A_ELT]
    __half* Bs = gsm + GSTG * G_A_ELT;         // [GSTG][G_B_ELT]

    const int z = blockIdx.z;
    const __half* A = Abase + (size_t)z * sA;
    const __half* W = Wbase + (size_t)z * sW;
    const float* bias = (z == 0) ? b0 : (z == 1) ? b1 : b2;
    OT* C = Cbase + (size_t)z * sC;
    const float sc = (z == 0) ? sc0 : (z == 1) ? sc1 : sc2;

    const int tid = threadIdx.x, lane = tid & 31, w = tid >> 5;
    const int wm = w >> 2, wn = w & 3;          // warp: rows wm*64, cols wn*32
    const int row0 = blockIdx.y * GBM, col0 = blockIdx.x * GBN;
    const int N = DIM, K = DIM;

    wmma::fragment<wmma::accumulator, 16, 16, 16, float> acc[4][2];
#pragma unroll
    for (int mf = 0; mf < 4; mf++)
#pragma unroll
        for (int nf = 0; nf < 2; nf++)
            wmma::fill_fragment(acc[mf][nf], 0.f);

    auto stage = [&](int buf, int kt) {
        __half* Ad = As + buf * G_A_ELT;
        __half* Bd = Bs + buf * G_B_ELT;
#pragma unroll
        for (int it = 0; it < 2; it++) {
            int c = tid + it * 256;
            int arow = c >> 2, acu = c & 3;
            cp16(smemu32(&Ad[arow * A_LDH + acu * 8]),
                 A + (size_t)(row0 + arow) * K + kt + acu * 8);
            int brow = c >> 4, bcu = c & 15;
            cp16(smemu32(&Bd[brow * B_LDH + bcu * 8]),
                 W + (size_t)(kt + brow) * N + col0 + bcu * 8);
        }
    };

    // prolog: fill 3 stages
#pragma unroll
    for (int s = 0; s < GSTG - 1; s++) {
        stage(s, s * GBK);
        cp_commit();
    }

    const int NIT = K / GBK;   // 32
    for (int i = 0; i < NIT; i++) {
        cp_wait2();
        __syncthreads();
        if (i + GSTG - 1 < NIT) stage((i + GSTG - 1) % GSTG, (i + GSTG - 1) * GBK);
        cp_commit();

        const __half* sAp = As + (i % GSTG) * G_A_ELT;
        const __half* sBp = Bs + (i % GSTG) * G_B_ELT;
#pragma unroll
        for (int ks = 0; ks < 2; ks++) {
            const int k0 = ks * 16;
            wmma::fragment<wmma::matrix_a, 16, 16, 16, __half, wmma::row_major> af[4];
            wmma::fragment<wmma::matrix_b, 16, 16, 16, __half, wmma::row_major> bf[2];
#pragma unroll
            for (int mf = 0; mf < 4; mf++)
                wmma::load_matrix_sync(af[mf], &sAp[(wm * 64 + mf * 16) * A_LDH + k0], A_LDH);
#pragma unroll
            for (int nf = 0; nf < 2; nf++)
                wmma::load_matrix_sync(bf[nf], &sBp[k0 * B_LDH + wn * 32 + nf * 16], B_LDH);
#pragma unroll
            for (int mf = 0; mf < 4; mf++)
#pragma unroll
                for (int nf = 0; nf < 2; nf++)
                    wmma::mma_sync(acc[mf][nf], af[mf], bf[nf], acc[mf][nf]);
        }
    }

    // epilogue: (acc + bias) * scale
    float2 bb[2][2];
#pragma unroll
    for (int nf = 0; nf < 2; nf++)
#pragma unroll
        for (int g = 0; g < 2; g++)
            bb[nf][g] = *reinterpret_cast<const float2*>(
                &bias[col0 + wn * 32 + nf * 16 + g * 8 + 2 * (lane & 3)]);

#pragma unroll
    for (int mf = 0; mf < 4; mf++) {
        const int r = row0 + wm * 64 + mf * 16 + (lane >> 2);
#pragma unroll
        for (int nf = 0; nf < 2; nf++) {
#pragma unroll
            for (int g = 0; g < 2; g++) {
                const int col = col0 + wn * 32 + nf * 16 + g * 8 + 2 * (lane & 3);
                float v0 = (acc[mf][nf].x[g * 4 + 0] + bb[nf][g].x) * sc;
                float v1 = (acc[mf][nf].x[g * 4 + 1] + bb[nf][g].y) * sc;
                float v2 = (acc[mf][nf].x[g * 4 + 2] + bb[nf][g].x) * sc;
                float v3 = (acc[mf][nf].x[g * 4 + 3] + bb[nf][g].y) * sc;
                if constexpr (__is_same(OT, float)) {
                    *reinterpret_cast<float2*>(&C[(size_t)r * N + col])       = make_float2(v0, v1);
                    *reinterpret_cast<float2*>(&C[(size_t)(r + 8) * N + col]) = make_float2(v2, v3);
                } else {
                    *reinterpret_cast<__half2*>(&C[(size_t)r * N + col])       = __floats2half2_rn(v0, v1);
                    *reinterpret_cast<__half2*>(&C[(size_t)(r + 8) * N + col]) = __floats2half2_rn(v2, v3);
                }
            }
        }
    }
}

// ---------------------------------------------------------------------------
// FA2-style masked attention on raw mma.m16n8k16.
// 8 warps x 16 Q rows (128-row Q tile), KV tile 64, 3-stage cp.async pipeline.
// S arrives in the log2 domain (log2e folded into Q scale) -> softmax
// numerator is ONE MUFU ex2 per value. Row-sum shuffles hoisted out of loop.
// ---------------------------------------------------------------------------
#define ALD 72
#define ASTG 3

__global__ __launch_bounds__(256, 2)
void attn_mma(__half* __restrict__ Og)
{
    extern __shared__ __half sm[];
    __half* Qs = sm;                    // [128][72]
    __half* Ks = Qs + 128 * ALD;        // [3][64][72]
    __half* Vs = Ks + ASTG * 64 * ALD;  // [3][64][72]

    const int qt = blockIdx.x, h = blockIdx.y, b = blockIdx.z;
    const int s0 = qt * 128;
    const int tid = threadIdx.x, lane = tid & 31, w = tid >> 5;
    const int grp = lane >> 2, tig = lane & 3;
    const int q0 = w * 16;

    const __half* Qb = g_QKVh + ((size_t)b * SEQ + s0) * DIM + h * HD;
    const __half* Kb = g_QKVh + (size_t)MTOT * DIM + (size_t)b * SEQ * DIM + h * HD;
    const __half* Vb = g_QKVh + 2 * (size_t)MTOT * DIM + (size_t)b * SEQ * DIM + h * HD;

    // stage Q tile (log2-domain scale pre-folded): 1024 uint4, 4/thread
#pragma unroll
    for (int it = 0; it < 4; it++) {
        int lin = tid + it * 256, r = lin >> 3, u = lin & 7;
        *reinterpret_cast<uint4*>(&Qs[r * ALD + u * 8]) =
            *reinterpret_cast<const uint4*>(Qb + (size_t)r * DIM + u * 8);
    }

    // cp.async KV staging: 512 chunks per matrix, 2/thread each
    const int kr0 = tid >> 3, ku = tid & 7, kr1 = kr0 + 32;
    auto stage_kv = [&](int buf, int kt) {
        __half* Kd = Ks + buf * 64 * ALD;
        __half* Vd = Vs + buf * 64 * ALD;
        cp16(smemu32(&Kd[kr0 * ALD + ku * 8]), Kb + (size_t)(kt + kr0) * DIM + ku * 8);
        cp16(smemu32(&Kd[kr1 * ALD + ku * 8]), Kb + (size_t)(kt + kr1) * DIM + ku * 8);
        cp16(smemu32(&Vd[kr0 * ALD + ku * 8]), Vb + (size_t)(kt + kr0) * DIM + ku * 8);
        cp16(smemu32(&Vd[kr1 * ALD + ku * 8]), Vb + (size_t)(kt + kr1) * DIM + ku * 8);
    };
    stage_kv(0, 0);
    cp_commit();
    stage_kv(1, 64);
    cp_commit();
    __syncthreads();   // Qs visible for ldmatrix

    // persistent Q A-fragments
    uint32_t qa[4][4];
#pragma unroll
    for (int di = 0; di < 4; di++) {
        uint32_t a = smemu32(&Qs[(q0 + (lane & 15)) * ALD + di * 16 + 8 * (lane >> 4)]);
        ldsm4(qa[di], a);
    }

    float o[8][4];
#pragma unroll
    for (int j = 0; j < 8; j++)
#pragma unroll
        for (int e = 0; e < 4; e++) o[j][e] = 0.f;
    float lsum0 = 0.f, lsum8 = 0.f;    // per-thread partials; reduced after loop

    const int mrow0 = (s0 + q0 + grp) * MBW;

    const int NIT = SEQ / 64;   // 32
    for (int i = 0; i < NIT; i++) {
        cp_wait1();
        __syncthreads();
        if (i + 2 < NIT) stage_kv((i + 2) % ASTG, (i + 2) * 64);
        cp_commit();

        const __half* Kt = Ks + (i % ASTG) * 64 * ALD;
        const __half* Vt = Vs + (i % ASTG) * 64 * ALD;
        const int kt = i * 64;

        // mask words for this warp's two row-halves
        const int wi = kt >> 5;
        uint32_t mlo0 = g_MB[mrow0 + wi],           mlo1 = g_MB[mrow0 + wi + 1];
        uint32_t mhi0 = g_MB[mrow0 + 8 * MBW + wi], mhi1 = g_MB[mrow0 + 8 * MBW + wi + 1];

        // ---- S = Q @ K^T (log2 domain) : 16 x 64 strip per warp ----
        float s[8][4];
#pragma unroll
        for (int j = 0; j < 8; j++)
#pragma unroll
            for (int e = 0; e < 4; e++) s[j][e] = 0.f;

#pragma unroll
        for (int di = 0; di < 4; di++) {
            const int d0 = di * 16;
            uint32_t kb[4][4];
#pragma unroll
            for (int ti = 0; ti < 4; ti++) {
                uint32_t a = smemu32(&Kt[(ti * 16 + (lane & 7) + 8 * (lane >> 4)) * ALD
                                         + d0 + 8 * ((lane >> 3) & 1)]);
                ldsm4(kb[ti], a);
            }
#pragma unroll
            for (int ti = 0; ti < 4; ti++) {
                const int j = 2 * ti;
                mma16816(s[j][0], s[j][1], s[j][2], s[j][3],
                         qa[di][0], qa[di][1], qa[di][2], qa[di][3], kb[ti][0], kb[ti][1]);
                mma16816(s[j + 1][0], s[j + 1][1], s[j + 1][2], s[j + 1][3],
                         qa[di][0], qa[di][1], qa[di][2], qa[di][3], kb[ti][2], kb[ti][3]);
            }
        }

        // ---- masked ex2 + row-sum partials + pack P (registers only) ----
        uint32_t ph[8][2];
#pragma unroll
        for (int j = 0; j < 8; j++) {
            uint32_t wlo = (j < 4) ? mlo0 : mlo1;
            uint32_t whi = (j < 4) ? mhi0 : mhi1;
            const int bit = (8 * j + 2 * tig) & 31;
            float p0 = ((wlo >> bit) & 1u)       ? ex2f(s[j][0]) : 0.f;
            float p1 = ((wlo >> (bit + 1)) & 1u) ? ex2f(s[j][1]) : 0.f;
            float p2 = ((whi >> bit) & 1u)       ? ex2f(s[j][2]) : 0.f;
            float p3 = ((whi >> (bit + 1)) & 1u) ? ex2f(s[j][3]) : 0.f;
            lsum0 += p0 + p1;
            lsum8 += p2 + p3;
            ph[j][0] = pack_h2(p0, p1);
            ph[j][1] = pack_h2(p2, p3);
        }

        // ---- O += P @ V (P from registers, V ldsm batched per ti) ----
#pragma unroll
        for (int ti = 0; ti < 4; ti++) {
            const int t0 = ti * 16, j = 2 * ti;
            uint32_t vb[4][4];
#pragma unroll
            for (int ni = 0; ni < 4; ni++) {
                uint32_t a = smemu32(&Vt[(t0 + (lane & 15)) * ALD + ni * 16 + 8 * (lane >> 4)]);
                ldsm4t(vb[ni], a);
            }
#pragma unroll
            for (int ni = 0; ni < 4; ni++) {
                const int jo = 2 * ni;
                mma16816(o[jo][0], o[jo][1], o[jo][2], o[jo][3],
                         ph[j][0], ph[j][1], ph[j + 1][0], ph[j + 1][1], vb[ni][0], vb[ni][1]);
                mma16816(o[jo + 1][0], o[jo + 1][1], o[jo + 1][2], o[jo + 1][3],
                         ph[j][0], ph[j][1], ph[j + 1][0], ph[j + 1][1], vb[ni][2], vb[ni][3]);
            }
        }
    }

    // ---- final row-sum reduction (once, not per tile) ----
    lsum0 += __shfl_xor_sync(0xffffffffu, lsum0, 1);
    lsum0 += __shfl_xor_sync(0xffffffffu, lsum0, 2);
    lsum8 += __shfl_xor_sync(0xffffffffu, lsum8, 1);
    lsum8 += __shfl_xor_sync(0xffffffffu, lsum8, 2);

    // ---- normalize + write half ctx ----
    const float inv0 = 1.f / lsum0;
    const float inv8 = 1.f / lsum8;
    __half* O0 = Og + ((size_t)b * SEQ + s0 + q0 + grp) * DIM + h * HD;
    __half* O8 = O0 + 8 * (size_t)DIM;
#pragma unroll
    for (int j = 0; j < 8; j++) {
        const int col = 8 * j + 2 * tig;
        *reinterpret_cast<__half2*>(&O0[col]) = __floats2half2_rn(o[j][0] * inv0, o[j][1] * inv0);
        *reinterpret_cast<__half2*>(&O8[col]) = __floats2half2_rn(o[j][2] * inv8, o[j][3] * inv8);
    }
}

// ---------------------------------------------------------------------------
// Launch
// ---------------------------------------------------------------------------
extern "C" void kernel_launch(void* const* d_in, const int* in_sizes, int n_in,
                              void* d_out, int out_size)
{
    const float* query = (const float*)d_in[0];
    const float* key   = (const float*)d_in[1];
    const float* value = (const float*)d_in[2];
    const int*   mask  = (const int*)  d_in[3];
    const float* Wq = (const float*)d_in[4];
    const float* bq = (const float*)d_in[5];
    const float* Wk = (const float*)d_in[6];
    const float* bk = (const float*)d_in[7];
    const float* Wv = (const float*)d_in[8];
    const float* bv = (const float*)d_in[9];
    const float* Wo = (const float*)d_in[10];
    const float* bo = (const float*)d_in[11];
    float* out = (float*)d_out;

    __half *pXh, *pWh, *pQKV, *pC;
    cudaGetSymbolAddress((void**)&pXh,  g_Xh);
    cudaGetSymbolAddress((void**)&pWh,  g_Wh);
    cudaGetSymbolAddress((void**)&pQKV, g_QKVh);
    cudaGetSymbolAddress((void**)&pC,   g_Ch);

    // pre-passes
    mask_bits_kernel<<<SEQ * SEQ / 256, 256>>>(mask);
    cvt_inputs<<<dim3(MTOT * DIM / 4 / 256, 3), 256>>>(query, key, value);
    cvt_weights<<<dim3(DIM * DIM / 4 / 256, 4), 256>>>(Wq, Wk, Wv, Wo);

    // fused QKV projections (all-half), log2-domain scale folded into Q
    cudaFuncSetAttribute(gemm_h<__half>, cudaFuncAttributeMaxDynamicSharedMemorySize, GEMM_SMEM);
    cudaFuncSetAttribute(gemm_h<float>,  cudaFuncAttributeMaxDynamicSharedMemorySize, GEMM_SMEM);
    dim3 qkv_grid(DIM / GBN, MTOT / GBM, 3);   // (8, 32, 3)
    gemm_h<__half><<<qkv_grid, 256, GEMM_SMEM>>>(
        pXh, (size_t)MTOT * DIM, pWh, (size_t)DIM * DIM,
        bq, bk, bv, pQKV, (size_t)MTOT * DIM,
        ATT_SCALE_LOG2E, 1.0f, 1.0f);

    // attention (3-stage KV pipeline, ex2-domain softmax)
    const int attn_smem = (128 + 2 * ASTG * 64) * ALD * (int)sizeof(__half);  // 73728 B
    cudaFuncSetAttribute(attn_mma, cudaFuncAttributeMaxDynamicSharedMemorySize, attn_smem);
    attn_mma<<<dim3(SEQ / 128, NH, BATCH), 256, attn_smem>>>(pC);

    // output projection (half A -> fp32 out)
    dim3 ogrid(DIM / GBN, MTOT / GBM, 1);
    gemm_h<float><<<ogrid, 256, GEMM_SMEM>>>(
        pC, 0, pWh + 3 * (size_t)DIM * DIM, 0,
        bo, bo, bo, out, 0,
        1.0f, 1.0f, 1.0f);
}